// round 1
// baseline (speedup 1.0000x reference)
#include <cuda_runtime.h>

#define DD 512
#define NN 128
#define TPB 256
#define TINYF 1e-30f

// Woodbury-reduced ordered Slater-determinant sampler.
//
// State: Rb = R[:, 0:N] where R = (I_m - U^T U)^{-1}, m <= 256.
// Thread r (0..255) holds row r of Rb in 128 registers.
// Per step i:
//   q = Rb @ P_row_i            (register matvec, P row broadcast from SMEM)
//   s = 1 - P_row_i . q[0:128]  (warp-0 reduction)
//   decision (thread 0): p = -(s-1)*ratio, occupy test, record outputs
//   Rb += (q * pivinv) q[0:128]^T   (rank-1, register update)
//   on occupy: row (128+k) activates via q[newrow] := 1 (its Rb row was all-zero)
__global__ __launch_bounds__(TPB, 1)
void slater_sampler_kernel(const float* __restrict__ P,
                           const float* __restrict__ uin,
                           float* __restrict__ out,
                           int out_size)
{
    __shared__ __align__(16) float sh_u[NN];
    __shared__ __align__(16) float sh_up[NN];
    __shared__ __align__(16) float sh_q[TPB];
    __shared__ float sh_pivinv;
    __shared__ int   sh_newrow;
    __shared__ int   sh_k;
    __shared__ float sh_ratio;
    __shared__ float sh_cumul;

    const int tid = threadIdx.x;

    // Init output: cond_probs region = 0, positions region = -1.
    const int pos_base = NN * DD;
    for (int idx = tid; idx < out_size; idx += TPB)
        out[idx] = (idx < pos_base) ? 0.0f : -1.0f;

    if (tid < NN) sh_u[tid] = uin[tid];
    if (tid == 0) { sh_k = 0; sh_ratio = 1.0f; sh_cumul = 0.0f; sh_newrow = -1; }

    // Rb row r in registers. Init: R = I_128 on top, zeros below.
    float rb[NN];
#pragma unroll
    for (int c = 0; c < NN; ++c)
        rb[c] = (c == tid) ? 1.0f : 0.0f;   // tid>=128 -> all zero

    __syncthreads();

    const bool write_pos = (pos_base + NN) <= out_size;

    for (int i = 0; i < DD; ++i) {
        // Load P row i into SMEM.
        if (tid < NN) sh_up[tid] = P[(size_t)i * NN + tid];
        __syncthreads();  // sync1: up visible; prev rank-1 q-reads done

        // Matvec: q_r = Rb[r,:] . up
        const float4* up4 = reinterpret_cast<const float4*>(sh_up);
        float a0 = 0.f, a1 = 0.f, a2 = 0.f, a3 = 0.f;
#pragma unroll
        for (int j = 0; j < NN / 4; ++j) {
            float4 uv = up4[j];
            a0 += rb[4 * j + 0] * uv.x;
            a1 += rb[4 * j + 1] * uv.y;
            a2 += rb[4 * j + 2] * uv.z;
            a3 += rb[4 * j + 3] * uv.w;
        }
        sh_q[tid] = (a0 + a1) + (a2 + a3);
        __syncthreads();  // sync2: q visible

        // Reduction + decision on warp 0.
        if (tid < 32) {
            float sp = 0.f;
#pragma unroll
            for (int t = 0; t < 4; ++t) {
                int r = tid * 4 + t;
                sp += sh_up[r] * sh_q[r];
            }
#pragma unroll
            for (int o = 16; o; o >>= 1)
                sp += __shfl_xor_sync(0xffffffffu, sp, o);

            if (tid == 0) {
                float s = 1.0f - sp;
                int   k     = sh_k;          // k < NN guaranteed (early exit below)
                float ratio = sh_ratio;
                float cumul = sh_cumul;
                int last_allowed = DD - NN + k;

                float p  = -(s - 1.0f) * ratio;
                float uk = sh_u[k];
                bool occupy = ((cumul + p) >= uk) || (i == last_allowed);

                float pivot = occupy ? (s - 1.0f) : s;
                if (fabsf(pivot) < TINYF) pivot = TINYF;

                out[k * DD + i] = p;          // cond_probs[k_before][i]
                if (occupy) {
                    if (write_pos) out[pos_base + k] = (float)i;
                    sh_newrow = NN + k;       // activate new dimension
                    sh_ratio  = 1.0f;
                    sh_cumul  = 0.0f;
                    sh_k      = k + 1;
                } else {
                    sh_newrow = -1;
                    sh_ratio  = ratio * s;
                    sh_cumul  = cumul + p;
                }
                sh_pivinv = 1.0f / pivot;
            }
        }
        __syncthreads();  // sync3: decision visible

        const int k_now = sh_k;
        if (k_now == NN && sh_newrow >= 0) {
            // Final occupation just happened; no future queries need Rb.
            break;
        }

        // Rank-1 update: Rb[r,:] += (q_r * pivinv) * q[0:128]
        float qr = sh_q[tid];
        if (tid == sh_newrow) qr = 1.0f;      // q_ext entry for the new row
        float scale = qr * sh_pivinv;

        const float4* q4 = reinterpret_cast<const float4*>(sh_q);
#pragma unroll
        for (int j = 0; j < NN / 4; ++j) {
            float4 qv = q4[j];
            rb[4 * j + 0] += scale * qv.x;
            rb[4 * j + 1] += scale * qv.y;
            rb[4 * j + 2] += scale * qv.z;
            rb[4 * j + 3] += scale * qv.w;
        }
    }
}

extern "C" void kernel_launch(void* const* d_in, const int* in_sizes, int n_in,
                              void* d_out, int out_size)
{
    const float* P = (const float*)d_in[0];   // (512, 128) row-major
    const float* u = (const float*)d_in[1];   // (128,)
    float* out = (float*)d_out;
    slater_sampler_kernel<<<1, TPB>>>(P, u, out, out_size);
}

// round 2
// speedup vs baseline: 1.1997x; 1.1997x over previous
#include <cuda_runtime.h>

#define DD 512
#define NN 128
#define TPB 256
#define TINYF 1e-30f

// ---- packed f32x2 helpers (Blackwell FFMA2) ----
__device__ __forceinline__ unsigned long long fma2(unsigned long long a,
                                                   unsigned long long b,
                                                   unsigned long long c) {
    unsigned long long d;
    asm("fma.rn.f32x2 %0, %1, %2, %3;" : "=l"(d) : "l"(a), "l"(b), "l"(c));
    return d;
}
__device__ __forceinline__ float lo2(unsigned long long v) {
    return __uint_as_float((unsigned)v);
}
__device__ __forceinline__ float hi2(unsigned long long v) {
    return __uint_as_float((unsigned)(v >> 32));
}
__device__ __forceinline__ unsigned long long pack2(float x, float y) {
    unsigned long long d;
    asm("mov.b64 %0, {%1, %2};" : "=l"(d) : "f"(x), "f"(y));
    return d;
}

// Woodbury-reduced ordered Slater-determinant sampler.
//
// State: Rb = R[:, 0:N], R = (I_m - U^T U)^{-1}, m <= 256 (128 P-rows + up to
// 128 occupation dims). Thread r holds row r of Rb as 64 packed f32x2 regs.
// Rows 128+k are exactly zero until occupation k activates them, so inactive
// threads skip both the matvec and the rank-1 entirely.
//
// Per step (2 barriers):
//   pre-B1 : prefetch next P row (tid>=128); matvec q_r = Rb[r,:] . up
//            (packed FFMA2); warps 0-3 butterfly-reduce up.q -> sh_part
//   B1
//   thread0: s = 1 - sum(part); occupy decision; pivinv; outputs
//   B2
//   post-B2: rank-1 Rb[r,:] += (q_r * pivinv) * q[0:128] (packed FFMA2);
//            new occupation row enters with q_ext = 1.
__global__ __launch_bounds__(TPB, 1)
void slater_sampler_kernel(const float* __restrict__ P,
                           const float* __restrict__ uin,
                           float* __restrict__ out,
                           int out_size)
{
    __shared__ __align__(16) float sh_up[2][NN];
    __shared__ __align__(16) float sh_q[2][NN];
    __shared__ __align__(16) float sh_part[4];
    __shared__ __align__(16) float sh_u[NN];
    __shared__ float sh_pivinv;
    __shared__ int   sh_newrow;
    __shared__ int   sh_k;

    const int tid = threadIdx.x;
    const int pos_base = NN * DD;

    // ---- init output: cond_probs = 0, positions = -1 ----
    {
        int n4 = out_size >> 2;
        float4* o4 = (float4*)out;
        for (int idx = tid; idx < n4; idx += TPB) {
            int base = idx * 4;
            float4 v;
            v.x = (base + 0 < pos_base) ? 0.0f : -1.0f;
            v.y = (base + 1 < pos_base) ? 0.0f : -1.0f;
            v.z = (base + 2 < pos_base) ? 0.0f : -1.0f;
            v.w = (base + 3 < pos_base) ? 0.0f : -1.0f;
            o4[idx] = v;
        }
        for (int idx = (n4 << 2) + tid; idx < out_size; idx += TPB)
            out[idx] = (idx < pos_base) ? 0.0f : -1.0f;
    }

    if (tid < NN) {
        sh_u[tid]     = uin[tid];
        sh_up[0][tid] = P[tid];          // P row 0
    }
    if (tid == 0) { sh_k = 0; sh_newrow = -1; }

    // Rb row in 64 packed f32x2 registers. Identity on top 128 rows.
    unsigned long long rb2[NN / 2];
#pragma unroll
    for (int j = 0; j < NN / 2; ++j) {
        unsigned long long v = 0ULL;
        if ((tid >> 1) == j)
            v = (tid & 1) ? 0x3f80000000000000ULL : 0x000000003f800000ULL;
        rb2[j] = v;
    }

    __syncthreads();

    const bool write_pos = (pos_base + NN) <= out_size;

    // thread-0 private sampler state
    float t0_ratio = 1.0f, t0_cumul = 0.0f;
    int   t0_k = 0;

    int kreg = 0;
    float qr = 0.0f;

    for (int i = 0; i < DD; ++i) {
        const int b = i & 1;
        const bool act = (tid < NN + kreg);

        // prefetch next P row (off critical path)
        float pf = 0.0f;
        const bool do_pf = (tid >= NN) && (i + 1 < DD);
        if (do_pf) pf = P[(size_t)(i + 1) * NN + (tid - NN)];

        // ---- matvec: q_r = Rb[r,:] . up ----
        qr = 0.0f;
        if (act) {
            const ulonglong2* up2 = reinterpret_cast<const ulonglong2*>(sh_up[b]);
            unsigned long long a0 = 0, a1 = 0, a2 = 0, a3 = 0;
#pragma unroll
            for (int j = 0; j < 16; ++j) {
                ulonglong2 ua = up2[2 * j];
                ulonglong2 ub = up2[2 * j + 1];
                a0 = fma2(rb2[4 * j + 0], ua.x, a0);
                a1 = fma2(rb2[4 * j + 1], ua.y, a1);
                a2 = fma2(rb2[4 * j + 2], ub.x, a2);
                a3 = fma2(rb2[4 * j + 3], ub.y, a3);
            }
            qr = ((lo2(a0) + hi2(a0)) + (lo2(a1) + hi2(a1)))
               + ((lo2(a2) + hi2(a2)) + (lo2(a3) + hi2(a3)));
            if (tid < NN) sh_q[b][tid] = qr;
        }

        // ---- partial reduction of up . q by warps 0-3 (pre-barrier) ----
        if (tid < NN) {
            float prod = qr * sh_up[b][tid];
#pragma unroll
            for (int o = 16; o; o >>= 1)
                prod += __shfl_xor_sync(0xffffffffu, prod, o);
            if ((tid & 31) == 0) sh_part[tid >> 5] = prod;
        }

        // store prefetched next row
        if (do_pf) sh_up[b ^ 1][tid - NN] = pf;

        __syncthreads();  // B1: q, partials, next up visible

        if (tid == 0) {
            float4 pv = *reinterpret_cast<const float4*>(sh_part);
            float s = 1.0f - ((pv.x + pv.y) + (pv.z + pv.w));

            int   k     = t0_k;
            float ratio = t0_ratio;
            float cumul = t0_cumul;
            int last_allowed = DD - NN + k;

            float p  = -(s - 1.0f) * ratio;
            float uk = sh_u[k];
            bool occupy = ((cumul + p) >= uk) || (i == last_allowed);

            float pivot = occupy ? (s - 1.0f) : s;
            if (fabsf(pivot) < TINYF) pivot = TINYF;

            out[k * DD + i] = p;
            if (occupy) {
                if (write_pos) out[pos_base + k] = (float)i;
                sh_newrow = NN + k;
                t0_ratio  = 1.0f;
                t0_cumul  = 0.0f;
                t0_k      = k + 1;
            } else {
                sh_newrow = -1;
                t0_ratio  = ratio * s;
                t0_cumul  = cumul + p;
            }
            sh_k = t0_k;
            sh_pivinv = 1.0f / pivot;
        }

        __syncthreads();  // B2: decision visible

        kreg = sh_k;
        if (kreg == NN) break;   // final occupation done; Rb never queried again

        // ---- rank-1: Rb[r,:] += (q_r * pivinv) * q[0:128] ----
        const int nr = sh_newrow;
        if (act || tid == nr) {
            float qq = (tid == nr) ? 1.0f : qr;
            float scale = qq * sh_pivinv;
            unsigned long long s2 = pack2(scale, scale);
            const ulonglong2* q2 = reinterpret_cast<const ulonglong2*>(sh_q[b]);
#pragma unroll
            for (int j = 0; j < 16; ++j) {
                ulonglong2 qa = q2[2 * j];
                ulonglong2 qb = q2[2 * j + 1];
                rb2[4 * j + 0] = fma2(s2, qa.x, rb2[4 * j + 0]);
                rb2[4 * j + 1] = fma2(s2, qa.y, rb2[4 * j + 1]);
                rb2[4 * j + 2] = fma2(s2, qb.x, rb2[4 * j + 2]);
                rb2[4 * j + 3] = fma2(s2, qb.y, rb2[4 * j + 3]);
            }
        }
    }
}

extern "C" void kernel_launch(void* const* d_in, const int* in_sizes, int n_in,
                              void* d_out, int out_size)
{
    const float* P = (const float*)d_in[0];   // (512, 128) row-major
    const float* u = (const float*)d_in[1];   // (128,)
    float* out = (float*)d_out;
    slater_sampler_kernel<<<1, TPB>>>(P, u, out, out_size);
}